// round 3
// baseline (speedup 1.0000x reference)
#include <cuda_runtime.h>

// ---------------------------------------------------------------------------
// GIN encoder, fully fused per layer:
//   layer k: [CSR gather (+BN-affine fold for k=1) -> MLP -> tanh -> BN sumsq
//             + pre-BN per-graph pool sums]  all in one kernel.
// BatchNorm + pooling resolved algebraically:
//   out[g] = scale * poolsum_preBN[g] + cnt[g] * shift
//   layer-1 input: sc0*(h0[n] + sum h0[src]) + (1+deg)*sh0   (x0 never stored)
// ---------------------------------------------------------------------------

#define MAX_N 100000
#define MAX_E 1000000
#define MAX_G 1024
#define DIM 64
#define BN_EPS 1e-5f
#define SCAN_BS 1024

// Scratch (device globals: no runtime allocation allowed)
__device__ __align__(16) float g_h0[MAX_N * DIM];     // layer-0 pre-BN act
__device__ __align__(16) float g_stats[DIM];          // sumsq
__device__ __align__(16) float g_scale[DIM];
__device__ __align__(16) float g_shift[DIM];
__device__ __align__(16) float g_pool[MAX_G * DIM];   // pre-BN per-graph sums
__device__ int g_cnt[MAX_G];

__device__ int g_rowptr[MAX_N + 1];
__device__ int g_cursor[MAX_N + 1];
__device__ int g_srcidx[MAX_E];
__device__ int g_bsums[(MAX_N + SCAN_BS - 1) / SCAN_BS + 1];

// ---------------- packed f32x2 helpers (sm_100+) ---------------------------
static __device__ __forceinline__ unsigned long long ffma2(
    unsigned long long a, unsigned long long b, unsigned long long c) {
    unsigned long long d;
    asm("fma.rn.f32x2 %0, %1, %2, %3;" : "=l"(d) : "l"(a), "l"(b), "l"(c));
    return d;
}
static __device__ __forceinline__ unsigned long long pack2(float x, float y) {
    unsigned long long r;
    asm("mov.b64 %0, {%1, %2};" : "=l"(r) : "f"(x), "f"(y));
    return r;
}
static __device__ __forceinline__ float2 unpack2(unsigned long long v) {
    float2 f;
    asm("mov.b64 {%0, %1}, %2;" : "=f"(f.x), "=f"(f.y) : "l"(v));
    return f;
}

// ---------------- CSR build ------------------------------------------------
__global__ void hist_kernel(const int* __restrict__ ei, int E) {
    int t = blockIdx.x * blockDim.x + threadIdx.x;
    if (t >= E) return;
    atomicAdd(&g_cursor[__ldg(ei + E + t)], 1);
}

__global__ void reduce_kernel(int N) {
    __shared__ int s[SCAN_BS];
    int i = threadIdx.x;
    int gi = blockIdx.x * SCAN_BS + i;
    s[i] = (gi < N) ? g_cursor[gi] : 0;
    __syncthreads();
    for (int off = SCAN_BS / 2; off > 0; off >>= 1) {
        if (i < off) s[i] += s[i + off];
        __syncthreads();
    }
    if (i == 0) g_bsums[blockIdx.x] = s[0];
}

// parallel exclusive scan of block sums (nb <= 128)
__global__ void scan_bsums_kernel(int nb) {
    __shared__ int s[128];
    int i = threadIdx.x;
    int v = (i < nb) ? g_bsums[i] : 0;
    s[i] = v;
    __syncthreads();
    for (int off = 1; off < 128; off <<= 1) {
        int t = (i >= off) ? s[i - off] : 0;
        __syncthreads();
        s[i] += t;
        __syncthreads();
    }
    if (i < nb) g_bsums[i] = s[i] - v;
}

__global__ void scan_final_kernel(int N) {
    __shared__ int s[SCAN_BS];
    int i = threadIdx.x;
    int gi = blockIdx.x * SCAN_BS + i;
    int val = (gi < N) ? g_cursor[gi] : 0;
    s[i] = val;
    __syncthreads();
    for (int off = 1; off < SCAN_BS; off <<= 1) {
        int t = (i >= off) ? s[i - off] : 0;
        __syncthreads();
        s[i] += t;
        __syncthreads();
    }
    int excl = s[i] - val;
    int rp = g_bsums[blockIdx.x] + excl;
    if (gi <= N) {
        g_rowptr[gi] = rp;
        if (gi < N) g_cursor[gi] = rp;
    }
}

__global__ void fill_kernel(const int* __restrict__ ei, int E) {
    int t = blockIdx.x * blockDim.x + threadIdx.x;
    if (t >= E) return;
    int s = __ldg(ei + t);
    int d = __ldg(ei + E + t);
    int pos = atomicAdd(&g_cursor[d], 1);
    g_srcidx[pos] = s;
}

__global__ void cnt_kernel(const int* __restrict__ batch, int N) {
    int t = blockIdx.x * blockDim.x + threadIdx.x;
    if (t >= N) return;
    atomicAdd(&g_cnt[__ldg(batch + t)], 1);
}

// ---------------- MLP stage (packed f32x2 FMA) -----------------------------
static __device__ __forceinline__ void mlp_stage(float* row,
                                                 const float* Ws,
                                                 const float* bs) {
    unsigned long long acc[32];
    const unsigned long long* bu =
        reinterpret_cast<const unsigned long long*>(bs);
#pragma unroll
    for (int j = 0; j < 32; j++) acc[j] = bu[j];

    for (int k = 0; k < DIM; k++) {
        float xk = row[k];
        unsigned long long xx = pack2(xk, xk);
        const ulonglong2* Wp =
            reinterpret_cast<const ulonglong2*>(Ws + (k << 6));
#pragma unroll
        for (int j = 0; j < 16; j++) {
            ulonglong2 w = Wp[j];
            acc[2 * j + 0] = ffma2(xx, w.x, acc[2 * j + 0]);
            acc[2 * j + 1] = ffma2(xx, w.y, acc[2 * j + 1]);
        }
    }
#pragma unroll
    for (int j = 0; j < 32; j++) {
        float2 v = unpack2(acc[j]);
        row[2 * j + 0] = tanhf(v.x);
        row[2 * j + 1] = tanhf(v.y);
    }
}

// ---------------- fused layer kernel ---------------------------------------
// 128 threads, 128 nodes per block.
// Phase 1: CSR gather (16 lanes/node, 8 nodes concurrent) into smem rows.
//          AFFINE: fold previous layer's BN (sc*(sum h) + (1+deg)*sh).
// Phase 2: MLP(64->64 tanh ->64 tanh) per thread on own row.
// Phase 3: WRITE_H: coalesced store of pre-BN h. BN sumsq + segmented
//          per-graph pre-BN pool sums (batch sorted).
#define FUSED_SMEM_FLOATS (4096 + 4096 + 64 + 64 + 128 * 65 + 128)
#define FUSED_SMEM_BYTES  (FUSED_SMEM_FLOATS * 4)

template <bool AFFINE, bool WRITE_H>
__global__ __launch_bounds__(128) void fused_layer_kernel(
    const float* __restrict__ xin,
    const float* __restrict__ W1, const float* __restrict__ b1,
    const float* __restrict__ W2, const float* __restrict__ b2,
    const int* __restrict__ batch, float* __restrict__ hout, int N) {
    extern __shared__ float sm[];
    float* W1s  = sm;                  // 4096
    float* W2s  = sm + 4096;           // 4096
    float* b1s  = sm + 8192;           // 64
    float* b2s  = sm + 8256;           // 64
    float* rows = sm + 8320;           // 128 * 65
    int*   bats = (int*)(sm + 8320 + 128 * 65);  // 128

    int tid  = threadIdx.x;
    int base = blockIdx.x * 128;

    for (int i = tid; i < 4096; i += 128) {
        W1s[i] = W1[i];
        W2s[i] = W2[i];
    }
    if (tid < 64) {
        b1s[tid] = b1[tid];
        b2s[tid] = b2[tid];
    }
    {
        int n = base + tid;
        bats[tid] = __ldg(batch + (n < N ? n : N - 1));
    }

    // Phase 1: gather
    {
        int group = tid >> 4;   // 0..7
        int c     = tid & 15;   // float4 lane
        const float4* x4 = reinterpret_cast<const float4*>(xin);
#pragma unroll 1
        for (int w = 0; w < 16; w++) {
            int nl = w * 8 + group;
            int node = base + nl;
            float4 acc = make_float4(0.f, 0.f, 0.f, 0.f);
            if (node < N) {
                int beg = __ldg(g_rowptr + node);
                int end = __ldg(g_rowptr + node + 1);
                acc = x4[node * 16 + c];
                int e = beg;
                for (; e + 1 < end; e += 2) {
                    int s0 = __ldg(g_srcidx + e);
                    int s1 = __ldg(g_srcidx + e + 1);
                    float4 v0 = x4[s0 * 16 + c];
                    float4 v1 = x4[s1 * 16 + c];
                    acc.x += v0.x + v1.x;
                    acc.y += v0.y + v1.y;
                    acc.z += v0.z + v1.z;
                    acc.w += v0.w + v1.w;
                }
                if (e < end) {
                    int s0 = __ldg(g_srcidx + e);
                    float4 v0 = x4[s0 * 16 + c];
                    acc.x += v0.x;
                    acc.y += v0.y;
                    acc.z += v0.z;
                    acc.w += v0.w;
                }
                if (AFFINE) {
                    float4 sc = reinterpret_cast<const float4*>(g_scale)[c];
                    float4 sh = reinterpret_cast<const float4*>(g_shift)[c];
                    float f = (float)(1 + end - beg);
                    acc.x = acc.x * sc.x + f * sh.x;
                    acc.y = acc.y * sc.y + f * sh.y;
                    acc.z = acc.z * sc.z + f * sh.z;
                    acc.w = acc.w * sc.w + f * sh.w;
                }
            }
            float* row = rows + nl * 65 + (c << 2);
            row[0] = acc.x;
            row[1] = acc.y;
            row[2] = acc.z;
            row[3] = acc.w;
        }
    }
    __syncthreads();

    // Phase 2: MLP on own row (invalid rows stay zero)
    if (base + tid < N) {
        float* myrow = rows + tid * 65;
        mlp_stage(myrow, W1s, b1s);
        mlp_stage(myrow, W2s, b2s);
    }
    __syncthreads();

    // Phase 3a: optional coalesced h store
    if (WRITE_H) {
        int gb = base * DIM;
        for (int i = tid; i < 128 * DIM; i += 128) {
            int r = i >> 6, c = i & 63;
            if (base + r < N) hout[gb + i] = rows[r * 65 + c];
        }
    }

    // Phase 3b: BN sumsq (threads 64..127) + segmented pool sums (0..63)
    if (tid < 64) {
        int j = tid;
        int cur = bats[0];
        float acc = 0.0f;
        for (int r = 0; r < 128; r++) {
            int g = bats[r];
            float v = rows[r * 65 + j];
            if (g != cur) {
                atomicAdd(&g_pool[cur * DIM + j], acc);
                acc = 0.0f;
                cur = g;
            }
            acc += v;
        }
        atomicAdd(&g_pool[cur * DIM + j], acc);
    } else {
        int j = tid - 64;
        float s = 0.0f;
        for (int r = 0; r < 128; r++) {
            float v = rows[r * 65 + j];
            s += v * v;
        }
        atomicAdd(&g_stats[j], s);
    }
}

// ---------------- BN finalize (mean from pool sums) ------------------------
__global__ void finalize_kernel(const float* __restrict__ gamma,
                                const float* __restrict__ beta,
                                float invN, int G) {
    int j = threadIdx.x;  // 64 threads
    float s = 0.0f;
    for (int g = 0; g < G; g++) s += g_pool[g * DIM + j];
    float mean = s * invN;
    float var  = g_stats[j] * invN - mean * mean;
    float sc   = gamma[j] * rsqrtf(var + BN_EPS);
    g_scale[j] = sc;
    g_shift[j] = beta[j] - mean * sc;
}

// ---------------- output epilogue ------------------------------------------
__global__ void outwrite_kernel(float* __restrict__ out, int col_off, int G) {
    int idx = blockIdx.x * blockDim.x + threadIdx.x;
    if (idx >= G * DIM) return;
    int g = idx >> 6, j = idx & 63;
    out[g * 128 + col_off + j] =
        g_scale[j] * g_pool[idx] + (float)g_cnt[g] * g_shift[j];
}

// ---------------------------------------------------------------------------
extern "C" void kernel_launch(void* const* d_in, const int* in_sizes, int n_in,
                              void* d_out, int out_size) {
    const float* x       = (const float*)d_in[0];
    const float* W1_0    = (const float*)d_in[1];
    const float* b1_0    = (const float*)d_in[2];
    const float* W2_0    = (const float*)d_in[3];
    const float* b2_0    = (const float*)d_in[4];
    const float* gamma_0 = (const float*)d_in[5];
    const float* beta_0  = (const float*)d_in[6];
    const float* W1_1    = (const float*)d_in[7];
    const float* b1_1    = (const float*)d_in[8];
    const float* W2_1    = (const float*)d_in[9];
    const float* b2_1    = (const float*)d_in[10];
    const float* gamma_1 = (const float*)d_in[11];
    const float* beta_1  = (const float*)d_in[12];
    const int*   ei      = (const int*)d_in[13];
    const int*   batch   = (const int*)d_in[14];

    int N = in_sizes[0] / DIM;
    int E = in_sizes[13] / 2;
    int G = out_size / 128;
    float* out = (float*)d_out;

    void *stats_p, *h0_p, *cursor_p, *pool_p, *cnt_p;
    cudaGetSymbolAddress(&stats_p, g_stats);
    cudaGetSymbolAddress(&h0_p, g_h0);
    cudaGetSymbolAddress(&cursor_p, g_cursor);
    cudaGetSymbolAddress(&pool_p, g_pool);
    cudaGetSymbolAddress(&cnt_p, g_cnt);

    cudaFuncSetAttribute(fused_layer_kernel<false, true>,
                         cudaFuncAttributeMaxDynamicSharedMemorySize,
                         FUSED_SMEM_BYTES);
    cudaFuncSetAttribute(fused_layer_kernel<true, false>,
                         cudaFuncAttributeMaxDynamicSharedMemorySize,
                         FUSED_SMEM_BYTES);

    int edge_blocks  = (E + 255) / 256;
    int nb_scan      = (N + SCAN_BS - 1) / SCAN_BS;
    int fused_blocks = (N + 127) / 128;
    int node_blocks  = (N + 255) / 256;
    int ow_blocks    = (G * DIM + 255) / 256;
    float invN = 1.0f / (float)N;

    // ---- CSR build + graph counts (shared by both layers) ----
    cudaMemsetAsync(cursor_p, 0, (size_t)(N + 1) * sizeof(int));
    cudaMemsetAsync(cnt_p, 0, (size_t)G * sizeof(int));
    hist_kernel<<<edge_blocks, 256>>>(ei, E);
    cnt_kernel<<<node_blocks, 256>>>(batch, N);
    reduce_kernel<<<nb_scan, SCAN_BS>>>(N);
    scan_bsums_kernel<<<1, 128>>>(nb_scan);
    scan_final_kernel<<<nb_scan, SCAN_BS>>>(N);
    fill_kernel<<<edge_blocks, 256>>>(ei, E);

    // ---------------- layer 0 ----------------
    cudaMemsetAsync(pool_p, 0, (size_t)G * DIM * sizeof(float));
    cudaMemsetAsync(stats_p, 0, DIM * sizeof(float));
    fused_layer_kernel<false, true><<<fused_blocks, 128, FUSED_SMEM_BYTES>>>(
        x, W1_0, b1_0, W2_0, b2_0, batch, (float*)h0_p, N);
    finalize_kernel<<<1, 64>>>(gamma_0, beta_0, invN, G);
    outwrite_kernel<<<ow_blocks, 256>>>(out, 0, G);

    // ---------------- layer 1 (reads pre-BN h0, folds BN0 affine) ----------
    cudaMemsetAsync(pool_p, 0, (size_t)G * DIM * sizeof(float));
    cudaMemsetAsync(stats_p, 0, DIM * sizeof(float));
    fused_layer_kernel<true, false><<<fused_blocks, 128, FUSED_SMEM_BYTES>>>(
        (const float*)h0_p, W1_1, b1_1, W2_1, b2_1, batch, nullptr, N);
    finalize_kernel<<<1, 64>>>(gamma_1, beta_1, invN, G);
    outwrite_kernel<<<ow_blocks, 256>>>(out, 64, G);
}

// round 4
// speedup vs baseline: 1.2752x; 1.2752x over previous
#include <cuda_runtime.h>

// ---------------------------------------------------------------------------
// GIN encoder. Split-kernel pipeline (round-2 structure) + algebraic BN fold:
//   CSR build (shared) ->
//   layer0: aggregate -> MLP(+BN sumsq+pre-BN pool sums) -> finalize+outwrite
//   layer1: aggregate(reads raw h0, folds BN0 affine) -> MLP(...) -> finalize
// BatchNorm+pool resolved algebraically:
//   out[g] = scale * poolsum_preBN[g] + cnt[g] * shift
//   hin1   = sc0*(h0[n] + sum h0[src]) + (1+deg)*sh0      (x0 never stored)
// ---------------------------------------------------------------------------

#define MAX_N 100000
#define MAX_E 1000000
#define MAX_G 1024
#define DIM 64
#define BN_EPS 1e-5f
#define SCAN_BS 1024

// Scratch (device globals; memset-friendly merged regions)
__device__ __align__(16) float g_h0 [MAX_N * DIM];             // layer-0 pre-BN h
__device__ __align__(16) float g_hin[MAX_N * DIM];             // MLP inputs
__device__ __align__(16) float g_poolstats[MAX_G * DIM + DIM]; // pool | sumsq
__device__ __align__(16) float g_scale[DIM];
__device__ __align__(16) float g_shift[DIM];

__device__ int g_ints[MAX_N + 1 + MAX_G];   // cursor | cnt
__device__ int g_rowptr[MAX_N + 1];
__device__ int g_srcidx[MAX_E];
__device__ int g_bsums[(MAX_N + SCAN_BS - 1) / SCAN_BS + 1];

#define CURSOR(i) g_ints[i]
#define CNT(i)    g_ints[MAX_N + 1 + (i)]
#define POOL      g_poolstats
#define STATS     (g_poolstats + MAX_G * DIM)

// ---------------- packed f32x2 helpers (sm_100+) ---------------------------
static __device__ __forceinline__ unsigned long long ffma2(
    unsigned long long a, unsigned long long b, unsigned long long c) {
    unsigned long long d;
    asm("fma.rn.f32x2 %0, %1, %2, %3;" : "=l"(d) : "l"(a), "l"(b), "l"(c));
    return d;
}
static __device__ __forceinline__ unsigned long long pack2(float x, float y) {
    unsigned long long r;
    asm("mov.b64 %0, {%1, %2};" : "=l"(r) : "f"(x), "f"(y));
    return r;
}
static __device__ __forceinline__ float2 unpack2(unsigned long long v) {
    float2 f;
    asm("mov.b64 {%0, %1}, %2;" : "=f"(f.x), "=f"(f.y) : "l"(v));
    return f;
}

// ---------------- CSR build + graph counts ---------------------------------
__global__ void hist_cnt_kernel(const int* __restrict__ ei,
                                const int* __restrict__ batch, int E, int N) {
    int t = blockIdx.x * blockDim.x + threadIdx.x;
    if (t < E) atomicAdd(&CURSOR(__ldg(ei + E + t)), 1);
    if (t < N) atomicAdd(&CNT(__ldg(batch + t)), 1);
}

__global__ void reduce_kernel(int N) {
    __shared__ int s[SCAN_BS];
    int i = threadIdx.x;
    int gi = blockIdx.x * SCAN_BS + i;
    s[i] = (gi < N) ? CURSOR(gi) : 0;
    __syncthreads();
    for (int off = SCAN_BS / 2; off > 0; off >>= 1) {
        if (i < off) s[i] += s[i + off];
        __syncthreads();
    }
    if (i == 0) g_bsums[blockIdx.x] = s[0];
}

// parallel exclusive scan of block sums (nb <= 128)
__global__ void scan_bsums_kernel(int nb) {
    __shared__ int s[128];
    int i = threadIdx.x;
    int v = (i < nb) ? g_bsums[i] : 0;
    s[i] = v;
    __syncthreads();
    for (int off = 1; off < 128; off <<= 1) {
        int t = (i >= off) ? s[i - off] : 0;
        __syncthreads();
        s[i] += t;
        __syncthreads();
    }
    if (i < nb) g_bsums[i] = s[i] - v;
}

__global__ void scan_final_kernel(int N) {
    __shared__ int s[SCAN_BS];
    int i = threadIdx.x;
    int gi = blockIdx.x * SCAN_BS + i;
    int val = (gi < N) ? CURSOR(gi) : 0;
    s[i] = val;
    __syncthreads();
    for (int off = 1; off < SCAN_BS; off <<= 1) {
        int t = (i >= off) ? s[i - off] : 0;
        __syncthreads();
        s[i] += t;
        __syncthreads();
    }
    int excl = s[i] - val;
    int rp = g_bsums[blockIdx.x] + excl;
    if (gi <= N) {
        g_rowptr[gi] = rp;
        if (gi < N) CURSOR(gi) = rp;
    }
}

__global__ void fill_kernel(const int* __restrict__ ei, int E) {
    int t = blockIdx.x * blockDim.x + threadIdx.x;
    if (t >= E) return;
    int s = __ldg(ei + t);
    int d = __ldg(ei + E + t);
    int pos = atomicAdd(&CURSOR(d), 1);
    g_srcidx[pos] = s;
}

// ---------------- aggregation (gather, no atomics) -------------------------
// 16 lanes per node (float4 columns), 8 nodes per 128-thread block.
template <bool AFFINE>
__global__ __launch_bounds__(128) void aggregate_kernel(
    const float* __restrict__ x, float* __restrict__ hout, int N) {
    int node = blockIdx.x * 8 + (threadIdx.x >> 4);
    int c = threadIdx.x & 15;
    if (node >= N) return;
    int beg = __ldg(g_rowptr + node);
    int end = __ldg(g_rowptr + node + 1);
    const float4* x4 = reinterpret_cast<const float4*>(x);
    float4 acc = x4[node * 16 + c];
    int e = beg;
    for (; e + 1 < end; e += 2) {
        int s0 = __ldg(g_srcidx + e);
        int s1 = __ldg(g_srcidx + e + 1);
        float4 v0 = x4[s0 * 16 + c];
        float4 v1 = x4[s1 * 16 + c];
        acc.x += v0.x + v1.x;
        acc.y += v0.y + v1.y;
        acc.z += v0.z + v1.z;
        acc.w += v0.w + v1.w;
    }
    if (e < end) {
        int s0 = __ldg(g_srcidx + e);
        float4 v0 = x4[s0 * 16 + c];
        acc.x += v0.x;
        acc.y += v0.y;
        acc.z += v0.z;
        acc.w += v0.w;
    }
    if (AFFINE) {
        float4 sc = reinterpret_cast<const float4*>(g_scale)[c];
        float4 sh = reinterpret_cast<const float4*>(g_shift)[c];
        float f = (float)(1 + end - beg);
        acc.x = acc.x * sc.x + f * sh.x;
        acc.y = acc.y * sc.y + f * sh.y;
        acc.z = acc.z * sc.z + f * sh.z;
        acc.w = acc.w * sc.w + f * sh.w;
    }
    reinterpret_cast<float4*>(hout)[node * 16 + c] = acc;
}

// ---------------- MLP stage (packed f32x2 FMA) -----------------------------
static __device__ __forceinline__ void mlp_stage(float* row,
                                                 const float* Ws,
                                                 const float* bs) {
    unsigned long long acc[32];
    const unsigned long long* bu =
        reinterpret_cast<const unsigned long long*>(bs);
#pragma unroll
    for (int j = 0; j < 32; j++) acc[j] = bu[j];

    for (int k = 0; k < DIM; k++) {
        float xk = row[k];
        unsigned long long xx = pack2(xk, xk);
        const ulonglong2* Wp =
            reinterpret_cast<const ulonglong2*>(Ws + (k << 6));
#pragma unroll
        for (int j = 0; j < 16; j++) {
            ulonglong2 w = Wp[j];
            acc[2 * j + 0] = ffma2(xx, w.x, acc[2 * j + 0]);
            acc[2 * j + 1] = ffma2(xx, w.y, acc[2 * j + 1]);
        }
    }
#pragma unroll
    for (int j = 0; j < 32; j++) {
        float2 v = unpack2(acc[j]);
        row[2 * j + 0] = tanhf(v.x);
        row[2 * j + 1] = tanhf(v.y);
    }
}

// ---------------- MLP + BN sumsq + pre-BN pool sums ------------------------
#define MLP_SMEM_FLOATS (4096 + 4096 + 64 + 64 + 128 * 65 + 128)
#define MLP_SMEM_BYTES  (MLP_SMEM_FLOATS * 4)

template <bool WRITE_H>
__global__ __launch_bounds__(128) void mlp_kernel(
    const float* __restrict__ hin,
    const float* __restrict__ W1, const float* __restrict__ b1,
    const float* __restrict__ W2, const float* __restrict__ b2,
    const int* __restrict__ batch, float* __restrict__ hout, int N) {
    extern __shared__ float sm[];
    float* W1s  = sm;                  // 4096
    float* W2s  = sm + 4096;           // 4096
    float* b1s  = sm + 8192;           // 64
    float* b2s  = sm + 8256;           // 64
    float* rows = sm + 8320;           // 128 * 65
    int*   bats = (int*)(sm + 8320 + 128 * 65);

    int tid  = threadIdx.x;
    int base = blockIdx.x * 128;
    int node = base + tid;

    for (int i = tid; i < 4096; i += 128) {
        W1s[i] = W1[i];
        W2s[i] = W2[i];
    }
    if (tid < 64) {
        b1s[tid] = b1[tid];
        b2s[tid] = b2[tid];
    }
    bats[tid] = __ldg(batch + (node < N ? node : N - 1));

    float* myrow = rows + tid * 65;
    if (node < N) {
        const float4* h4 = reinterpret_cast<const float4*>(hin);
#pragma unroll
        for (int c = 0; c < 16; c++) {
            float4 v = h4[node * 16 + c];
            myrow[4 * c + 0] = v.x;
            myrow[4 * c + 1] = v.y;
            myrow[4 * c + 2] = v.z;
            myrow[4 * c + 3] = v.w;
        }
    } else {
#pragma unroll
        for (int c = 0; c < DIM; c++) myrow[c] = 0.0f;
    }
    __syncthreads();

    if (node < N) {
        mlp_stage(myrow, W1s, b1s);
        mlp_stage(myrow, W2s, b2s);
    }
    __syncthreads();

    if (WRITE_H) {
        int gb = base * DIM;
        for (int i = tid; i < 128 * DIM; i += 128) {
            int r = i >> 6, c = i & 63;
            if (base + r < N) hout[gb + i] = rows[r * 65 + c];
        }
    }

    // BN sumsq (threads 64..127) + segmented pre-BN pool sums (0..63);
    // padded rows are zero and contribute nothing.
    if (tid < 64) {
        int j = tid;
        int cur = bats[0];
        float acc = 0.0f;
        for (int r = 0; r < 128; r++) {
            int g = bats[r];
            float v = rows[r * 65 + j];
            if (g != cur) {
                atomicAdd(&POOL[cur * DIM + j], acc);
                acc = 0.0f;
                cur = g;
            }
            acc += v;
        }
        atomicAdd(&POOL[cur * DIM + j], acc);
    } else {
        int j = tid - 64;
        float s = 0.0f;
        for (int r = 0; r < 128; r++) {
            float v = rows[r * 65 + j];
            s += v * v;
        }
        atomicAdd(&STATS[j], s);
    }
}

// ---------------- finalize BN + write output block -------------------------
__global__ __launch_bounds__(512) void finalize_out_kernel(
    const float* __restrict__ gamma, const float* __restrict__ beta,
    float* __restrict__ out, int col_off, float invN, int G) {
    __shared__ float psum[8][64];
    __shared__ float scs[64], shs[64];
    int tid = threadIdx.x;
    int j = tid & 63;
    int sl = tid >> 6;  // 0..7

    float s = 0.0f;
    for (int g = sl; g < G; g += 8) s += POOL[g * DIM + j];
    psum[sl][j] = s;
    __syncthreads();
    if (tid < 64) {
        float m = 0.0f;
#pragma unroll
        for (int k = 0; k < 8; k++) m += psum[k][j];
        float mean = m * invN;
        float var  = STATS[j] * invN - mean * mean;
        float sc   = gamma[j] * rsqrtf(var + BN_EPS);
        float sh   = beta[j] - mean * sc;
        scs[j] = sc;
        shs[j] = sh;
        g_scale[j] = sc;
        g_shift[j] = sh;
    }
    __syncthreads();
    float sc = scs[j], sh = shs[j];
    for (int g = sl; g < G; g += 8) {
        out[g * 128 + col_off + j] =
            sc * POOL[g * DIM + j] + (float)CNT(g) * sh;
    }
}

// ---------------------------------------------------------------------------
extern "C" void kernel_launch(void* const* d_in, const int* in_sizes, int n_in,
                              void* d_out, int out_size) {
    const float* x       = (const float*)d_in[0];
    const float* W1_0    = (const float*)d_in[1];
    const float* b1_0    = (const float*)d_in[2];
    const float* W2_0    = (const float*)d_in[3];
    const float* b2_0    = (const float*)d_in[4];
    const float* gamma_0 = (const float*)d_in[5];
    const float* beta_0  = (const float*)d_in[6];
    const float* W1_1    = (const float*)d_in[7];
    const float* b1_1    = (const float*)d_in[8];
    const float* W2_1    = (const float*)d_in[9];
    const float* b2_1    = (const float*)d_in[10];
    const float* gamma_1 = (const float*)d_in[11];
    const float* beta_1  = (const float*)d_in[12];
    const int*   ei      = (const int*)d_in[13];
    const int*   batch   = (const int*)d_in[14];

    int N = in_sizes[0] / DIM;
    int E = in_sizes[13] / 2;
    int G = out_size / 128;
    float* out = (float*)d_out;

    void *ints_p, *ps_p, *h0_p, *hin_p;
    cudaGetSymbolAddress(&ints_p, g_ints);
    cudaGetSymbolAddress(&ps_p, g_poolstats);
    cudaGetSymbolAddress(&h0_p, g_h0);
    cudaGetSymbolAddress(&hin_p, g_hin);

    cudaFuncSetAttribute(mlp_kernel<true>,
                         cudaFuncAttributeMaxDynamicSharedMemorySize,
                         MLP_SMEM_BYTES);
    cudaFuncSetAttribute(mlp_kernel<false>,
                         cudaFuncAttributeMaxDynamicSharedMemorySize,
                         MLP_SMEM_BYTES);

    int edge_blocks = (E + 255) / 256;
    int nb_scan     = (N + SCAN_BS - 1) / SCAN_BS;
    int agg_blocks  = (N + 7) / 8;
    int mlp_blocks  = (N + 127) / 128;
    size_t ps_bytes = (size_t)(MAX_G * DIM + DIM) * sizeof(float);
    float invN = 1.0f / (float)N;

    // ---- CSR build + graph counts (shared by both layers) ----
    cudaMemsetAsync(ints_p, 0, sizeof(int) * (MAX_N + 1 + MAX_G));
    hist_cnt_kernel<<<edge_blocks, 256>>>(ei, batch, E, N);
    reduce_kernel<<<nb_scan, SCAN_BS>>>(N);
    scan_bsums_kernel<<<1, 128>>>(nb_scan);
    scan_final_kernel<<<nb_scan, SCAN_BS>>>(N);
    fill_kernel<<<edge_blocks, 256>>>(ei, E);

    // ---------------- layer 0 ----------------
    cudaMemsetAsync(ps_p, 0, ps_bytes);
    aggregate_kernel<false><<<agg_blocks, 128>>>(x, (float*)hin_p, N);
    mlp_kernel<true><<<mlp_blocks, 128, MLP_SMEM_BYTES>>>(
        (const float*)hin_p, W1_0, b1_0, W2_0, b2_0, batch, (float*)h0_p, N);
    finalize_out_kernel<<<1, 512>>>(gamma_0, beta_0, out, 0, invN, G);

    // ---------------- layer 1 (reads raw h0, folds BN0 affine) -------------
    cudaMemsetAsync(ps_p, 0, ps_bytes);
    aggregate_kernel<true><<<agg_blocks, 128>>>(
        (const float*)h0_p, (float*)hin_p, N);
    mlp_kernel<false><<<mlp_blocks, 128, MLP_SMEM_BYTES>>>(
        (const float*)hin_p, W1_1, b1_1, W2_1, b2_1, batch, nullptr, N);
    finalize_out_kernel<<<1, 512>>>(gamma_1, beta_1, out, 64, invN, G);
}